// round 5
// baseline (speedup 1.0000x reference)
#include <cuda_runtime.h>
#include <cstdint>

// Problem constants
#define B_TOTAL  128
#define C_IN     32
#define C_OUT    8
#define S_TOTAL  8192

// Tiling
#define S_TILE   64      // s-values per block (16 float4 groups)
#define B_CHUNK  16      // batches per block
#define THREADS  128

typedef unsigned long long ull;

// Scratch for ws[j,s] = sum_i w1[i,j,s]  (1 MB)
__device__ float g_ws[C_IN * S_TOTAL];

// ---------------------------------------------------------------------------
// helpers
// ---------------------------------------------------------------------------
__device__ __forceinline__ float tanh_fast(float x) {
    float y;
    asm("tanh.approx.f32 %0, %1;" : "=f"(y) : "f"(x));
    return y;
}

// Accurate tanh for final output: tanh(x) = 1 - 2/(e^{2x}+1)
__device__ __forceinline__ float tanh_acc(float x) {
    float xc = fminf(fmaxf(x, -20.0f), 20.0f);
    float e  = __expf(2.0f * xc);
    float r  = __frcp_rn(e + 1.0f);
    return fmaf(-2.0f, r, 1.0f);
}

__device__ __forceinline__ float4 ld4(const float* p) {
    return *reinterpret_cast<const float4*>(p);
}

__device__ __forceinline__ float4 tanh4_of_prod(float4 a, float4 b) {
    float4 r;
    r.x = tanh_fast(a.x * b.x);
    r.y = tanh_fast(a.y * b.y);
    r.z = tanh_fast(a.z * b.z);
    r.w = tanh_fast(a.w * b.w);
    return r;
}

// Blackwell packed f32x2 ops
__device__ __forceinline__ ull ffma2(ull a, ull b, ull c) {
    ull d;
    asm("fma.rn.f32x2 %0, %1, %2, %3;" : "=l"(d) : "l"(a), "l"(b), "l"(c));
    return d;
}
__device__ __forceinline__ ull add2(ull a, ull b) {
    ull d;
    asm("add.rn.f32x2 %0, %1, %2;" : "=l"(d) : "l"(a), "l"(b));
    return d;
}

__device__ __forceinline__ ulonglong2 add2v(ulonglong2 a, ulonglong2 b) {
    ulonglong2 r; r.x = add2(a.x, b.x); r.y = add2(a.y, b.y); return r;
}
__device__ __forceinline__ ulonglong2 shfl_xor2v(ulonglong2 v, int m) {
    ulonglong2 r;
    r.x = __shfl_xor_sync(0xffffffffu, v.x, m);
    r.y = __shfl_xor_sync(0xffffffffu, v.y, m);
    return r;
}
__device__ __forceinline__ ulonglong2 sel2v(bool c, ulonglong2 a, ulonglong2 b) {
    ulonglong2 r; r.x = c ? a.x : b.x; r.y = c ? a.y : b.y; return r;
}

// smem column swizzle: depends only on j>>3 (the jq chunk)
__device__ __forceinline__ int sigma_of(int jq) {
    return jq | ((jq & 1) << 2);
}

// ---------------------------------------------------------------------------
// Kernel 1: ws[j,s] = sum_i w1[i,j,s]      w1: [C_IN(i)][C_IN(j)][S]
// ---------------------------------------------------------------------------
__global__ __launch_bounds__(256) void ws_kernel(const float* __restrict__ w1) {
    int t = blockIdx.x * blockDim.x + threadIdx.x;   // 0 .. C_IN*S/4 - 1
    int j   = t >> 11;             // 2048 float4 groups per j row
    int grp = t & 2047;
    const float* p = w1 + (size_t)j * S_TOTAL + grp * 4;
    float4 acc = make_float4(0.f, 0.f, 0.f, 0.f);
#pragma unroll
    for (int i = 0; i < C_IN; i++) {
        float4 v = ld4(p + (size_t)i * C_IN * S_TOTAL);
        acc.x += v.x; acc.y += v.y; acc.z += v.z; acc.w += v.w;
    }
    *reinterpret_cast<float4*>(&g_ws[(size_t)j * S_TOTAL + grp * 4]) = acc;
}

// ---------------------------------------------------------------------------
// Kernel 2: fused stage1 + stage2.
//
// Phase-B decode: t = sg(16)*8 | og(2)*4 | jq(4)
//   thread owns outputs o = 4og..4og+3, j-chunk jq (j = 8jq..8jq+7), s4 = sg.
//   w2 regs: 4 o x 8 j float4 = 128 regs (as 64 ull, packed f32x2).
//   Each h LDS.128 feeds 16 FMAs (4 o); amp = 2 threads per h element.
//   Two butterfly stages over lanes' jq bits combine the j-chunks; final
//   lane jq holds o = 4og+jq.
// Phase-A decode: t = jA0(8)*16 | gA(16); thread produces h for
//   j = jA0+8k (k=0..3) at f4-column gA.  16 consecutive f4 per row ->
//   256B contiguous x loads and conflict-free STS.
// ---------------------------------------------------------------------------
__global__ void __launch_bounds__(THREADS) fused_kernel(
    const float* __restrict__ x,     // [B][C_IN][S]
    const float* __restrict__ w2,    // [C_OUT][C_IN][S]
    const float* __restrict__ bias,  // [C_OUT][S]
    float* __restrict__ out)         // [B][C_OUT][S]
{
    __shared__ float4 hb[2][C_IN][S_TILE / 4];   // 2 x 8 KB

    const int t     = threadIdx.x;
    const int sBase = blockIdx.x * S_TILE;
    const int bBase = blockIdx.y * B_CHUNK;

    // phase-B ids
    const int jq = t & 3;            // j-chunk 0..3
    const int og = (t >> 2) & 1;     // output group (o base = 4og)
    const int sg = t >> 3;           // s4-group 0..15
    const int o_final = 4 * og + jq; // this lane's output after reduction
    const int sigB = sigma_of(jq);

    // phase-A ids
    const int gA  = t & 15;          // f4 column 0..15
    const int jA0 = t >> 4;          // 0..7 ; handles j = jA0 + 8k

    // ws regs for phase A (block-invariant)
    float4 wsr[4];
#pragma unroll
    for (int k = 0; k < 4; k++)
        wsr[k] = ld4(&g_ws[(size_t)(jA0 + 8 * k) * S_TOTAL + sBase + gA * 4]);

    // w2 regs: 4 o x 8 j, packed as f32x2 pairs
    ulonglong2 w2r[4][8];
#pragma unroll
    for (int m = 0; m < 4; m++) {
        const float* p0 = w2 + ((size_t)(4 * og + m) * C_IN + jq * 8) * S_TOTAL
                             + sBase + sg * 4;
#pragma unroll
        for (int jj = 0; jj < 8; jj++)
            w2r[m][jj] = *reinterpret_cast<const ulonglong2*>(p0 + (size_t)jj * S_TOTAL);
    }

    // bias for this lane's final output
    const float4 biasr = ld4(&bias[(size_t)o_final * S_TOTAL + sBase + sg * 4]);

    // x stream
    const float* xrow = x + ((size_t)bBase * C_IN + jA0) * S_TOTAL + sBase + gA * 4;
    const size_t jstep = (size_t)8 * S_TOTAL;       // j += 8
    const size_t bstep = (size_t)C_IN * S_TOTAL;    // b += 1

    // produce h(0) into buffer 0
    float4 xr[4];
#pragma unroll
    for (int k = 0; k < 4; k++) xr[k] = ld4(xrow + k * jstep);
#pragma unroll
    for (int k = 0; k < 4; k++)
        hb[0][jA0 + 8 * k][gA ^ sigma_of(k)] = tanh4_of_prod(xr[k], wsr[k]);
    // prefetch x(1)
    xrow += bstep;
#pragma unroll
    for (int k = 0; k < 4; k++) xr[k] = ld4(xrow + k * jstep);

    for (int b = 0; b < B_CHUNK; b++) {
        __syncthreads();                 // h(b) ready in hb[b&1]
        const int p = b & 1;

        // produce h(b+1) into other buffer; prefetch x(b+2)
        if (b + 1 < B_CHUNK) {
#pragma unroll
            for (int k = 0; k < 4; k++)
                hb[p ^ 1][jA0 + 8 * k][gA ^ sigma_of(k)] = tanh4_of_prod(xr[k], wsr[k]);
            if (b + 2 < B_CHUNK) {
                xrow += bstep;
#pragma unroll
                for (int k = 0; k < 4; k++) xr[k] = ld4(xrow + k * jstep);
            }
        }

        // phase B: partials for 4 outputs over this thread's 8 j values
        ulonglong2 acc[4];
#pragma unroll
        for (int m = 0; m < 4; m++) { acc[m].x = 0ull; acc[m].y = 0ull; }

#pragma unroll
        for (int jj = 0; jj < 8; jj++) {
            const int j = jq * 8 + jj;
            ulonglong2 h2 = *reinterpret_cast<const ulonglong2*>(&hb[p][j][sg ^ sigB]);
#pragma unroll
            for (int m = 0; m < 4; m++) {
                acc[m].x = ffma2(h2.x, w2r[m][jj].x, acc[m].x);
                acc[m].y = ffma2(h2.y, w2r[m][jj].y, acc[m].y);
            }
        }

        // butterfly over jq lane bits: final lane jq holds o = 4og+jq
        const bool odd = (jq & 1) != 0;
        const bool hi  = (jq & 2) != 0;
        // stage 1 (xor 1): keep m with m&1 == jq&1
        ulonglong2 sendA = sel2v(odd, acc[0], acc[1]);
        ulonglong2 sendB = sel2v(odd, acc[2], acc[3]);
        ulonglong2 rA = shfl_xor2v(sendA, 1);
        ulonglong2 rB = shfl_xor2v(sendB, 1);
        ulonglong2 u0 = add2v(sel2v(odd, acc[1], acc[0]), rA);
        ulonglong2 u1 = add2v(sel2v(odd, acc[3], acc[2]), rB);
        // stage 2 (xor 2): keep m with m&2 == jq&2
        ulonglong2 sendC = sel2v(hi, u0, u1);
        ulonglong2 rC = shfl_xor2v(sendC, 2);
        ulonglong2 resv = add2v(sel2v(hi, u1, u0), rC);

        // unpack, add bias, outer tanh, store
        float2 lo = *reinterpret_cast<float2*>(&resv.x);
        float2 hi2 = *reinterpret_cast<float2*>(&resv.y);
        float4 ov;
        ov.x = tanh_acc(lo.x  + biasr.x);
        ov.y = tanh_acc(lo.y  + biasr.y);
        ov.z = tanh_acc(hi2.x + biasr.z);
        ov.w = tanh_acc(hi2.y + biasr.w);
        *reinterpret_cast<float4*>(
            &out[((size_t)(bBase + b) * C_OUT + o_final) * S_TOTAL + sBase + sg * 4]) = ov;
    }
}

// ---------------------------------------------------------------------------
// launch
// ---------------------------------------------------------------------------
extern "C" void kernel_launch(void* const* d_in, const int* in_sizes, int n_in,
                              void* d_out, int out_size) {
    const float* x    = (const float*)d_in[0];
    const float* w1   = (const float*)d_in[1];
    const float* w2   = (const float*)d_in[2];
    const float* bias = (const float*)d_in[3];
    float* out = (float*)d_out;

    ws_kernel<<<(C_IN * S_TOTAL / 4) / 256, 256>>>(w1);

    dim3 grid(S_TOTAL / S_TILE, B_TOTAL / B_CHUNK);   // (128, 8) = 1024 blocks
    fused_kernel<<<grid, THREADS>>>(x, w2, bias, out);
}

// round 6
// speedup vs baseline: 1.5882x; 1.5882x over previous
#include <cuda_runtime.h>
#include <cstdint>

// Problem constants
#define B_TOTAL  128
#define C_IN     32
#define C_OUT    8
#define S_TOTAL  8192

// Tiling for fused kernel
#define S_TILE    32     // s-values per block = 8 float4 groups
#define SG        8      // float4 groups per block
#define B_PER_BLK 16     // batches per block
#define THREADS   128    // SG * B_PER_BLK

// Scratch for ws[j,s] = sum_i w1[i,j,s]  (1 MB)
__device__ float g_ws[C_IN * S_TOTAL];

// ---------------------------------------------------------------------------
// helpers
// ---------------------------------------------------------------------------
__device__ __forceinline__ float tanh_fast(float x) {
    float y;
    asm("tanh.approx.f32 %0, %1;" : "=f"(y) : "f"(x));
    return y;
}

// Accurate tanh for final output: tanh(x) = 1 - 2/(e^{2x}+1)
__device__ __forceinline__ float tanh_acc(float x) {
    float xc = fminf(fmaxf(x, -20.0f), 20.0f);
    float e  = __expf(2.0f * xc);
    float r  = __frcp_rn(e + 1.0f);
    return fmaf(-2.0f, r, 1.0f);
}

__device__ __forceinline__ float4 ld4(const float* p) {
    return *reinterpret_cast<const float4*>(p);
}

__device__ __forceinline__ float4 tanh4_of_prod(float4 a, float4 b) {
    float4 r;
    r.x = tanh_fast(a.x * b.x);
    r.y = tanh_fast(a.y * b.y);
    r.z = tanh_fast(a.z * b.z);
    r.w = tanh_fast(a.w * b.w);
    return r;
}

__device__ __forceinline__ void fma4(float4& acc, float4 h, float4 w) {
    acc.x = fmaf(h.x, w.x, acc.x);
    acc.y = fmaf(h.y, w.y, acc.y);
    acc.z = fmaf(h.z, w.z, acc.z);
    acc.w = fmaf(h.w, w.w, acc.w);
}

// ---------------------------------------------------------------------------
// Kernel 1: ws[j,s] = sum_i w1[i,j,s]      w1: [C_IN(i)][C_IN(j)][S]
// ---------------------------------------------------------------------------
__global__ __launch_bounds__(256) void ws_kernel(const float* __restrict__ w1) {
    int t = blockIdx.x * blockDim.x + threadIdx.x;   // 0 .. C_IN*S/4 - 1
    int j   = t >> 11;             // 2048 float4 groups per j row
    int grp = t & 2047;
    const float* p = w1 + (size_t)j * S_TOTAL + grp * 4;
    float4 acc = make_float4(0.f, 0.f, 0.f, 0.f);
#pragma unroll
    for (int i = 0; i < C_IN; i++) {
        float4 v = ld4(p + (size_t)i * C_IN * S_TOTAL);
        acc.x += v.x; acc.y += v.y; acc.z += v.z; acc.w += v.w;
    }
    *reinterpret_cast<float4*>(&g_ws[(size_t)j * S_TOTAL + grp * 4]) = acc;
}

// ---------------------------------------------------------------------------
// Kernel 2: fused stage1 + stage2, no h exchange.
//
// Thread = (sg = t&7 : float4 column, bt = t>>3 : batch). Each thread:
//   acc[o] = bias[o]                          (8 float4 accumulators)
//   for j in 0..31:
//     x   = LDG x[b][j][s4]                    (x read exactly once, chipwide)
//     h   = tanh(x * ws_smem[j][sg])           (computed in registers)
//     acc[o] += h * w2_smem[o][j][sg]          (8 fma4 from smem)
//   out[b][o][s4] = tanh(acc[o])
//
// w2/ws tiles are loaded into smem ONCE per block and reused across all
// 16 batches. All warp smem reads are 128B-contiguous (8 consecutive f4,
// bt lanes broadcast) => conflict-free single-phase LDS.
// ---------------------------------------------------------------------------
__global__ void __launch_bounds__(THREADS) fused_kernel(
    const float* __restrict__ x,     // [B][C_IN][S]
    const float* __restrict__ w2,    // [C_OUT][C_IN][S]
    const float* __restrict__ bias,  // [C_OUT][S]
    float* __restrict__ out)         // [B][C_OUT][S]
{
    __shared__ float4 w2s[C_OUT * C_IN * SG];  // 2048 f4 = 32 KB
    __shared__ float4 wss[C_IN * SG];          //  256 f4 =  4 KB

    const int t     = threadIdx.x;
    const int sBase = blockIdx.x * S_TILE;
    const int bt    = t >> 3;                  // 0..15
    const int sg    = t & 7;                   // 0..7
    const int b     = blockIdx.y * B_PER_BLK + bt;

    // ---- preamble: cooperative load of w2 / ws tiles into smem ----
    // w2s[idx] with idx = ((o*32 + j) * 8 + sgl); global row stride S_TOTAL.
#pragma unroll
    for (int k = 0; k < (C_OUT * C_IN * SG) / THREADS; k++) {   // 16 iters
        int idx = t + k * THREADS;
        int row = idx >> 3;           // o*32 + j
        int sgl = idx & 7;
        w2s[idx] = ld4(w2 + (size_t)row * S_TOTAL + sBase + sgl * 4);
    }
#pragma unroll
    for (int k = 0; k < (C_IN * SG) / THREADS; k++) {           // 2 iters
        int idx = t + k * THREADS;
        int row = idx >> 3;
        int sgl = idx & 7;
        wss[idx] = ld4(&g_ws[(size_t)row * S_TOTAL + sBase + sgl * 4]);
    }
    __syncthreads();

    // ---- accumulators init from bias ----
    float4 acc[C_OUT];
#pragma unroll
    for (int o = 0; o < C_OUT; o++)
        acc[o] = ld4(bias + (size_t)o * S_TOTAL + sBase + sg * 4);

    // ---- main loop over j: fully independent per thread ----
    const float* xp = x + ((size_t)b * C_IN) * S_TOTAL + sBase + sg * 4;
#pragma unroll 8
    for (int j = 0; j < C_IN; j++) {
        float4 xv = ld4(xp + (size_t)j * S_TOTAL);
        float4 h  = tanh4_of_prod(xv, wss[j * SG + sg]);
#pragma unroll
        for (int o = 0; o < C_OUT; o++)
            fma4(acc[o], h, w2s[(o * C_IN + j) * SG + sg]);
    }

    // ---- epilogue: outer tanh + store ----
    float* op = out + ((size_t)b * C_OUT) * S_TOTAL + sBase + sg * 4;
#pragma unroll
    for (int o = 0; o < C_OUT; o++) {
        float4 ov;
        ov.x = tanh_acc(acc[o].x);
        ov.y = tanh_acc(acc[o].y);
        ov.z = tanh_acc(acc[o].z);
        ov.w = tanh_acc(acc[o].w);
        *reinterpret_cast<float4*>(op + (size_t)o * S_TOTAL) = ov;
    }
}

// ---------------------------------------------------------------------------
// launch
// ---------------------------------------------------------------------------
extern "C" void kernel_launch(void* const* d_in, const int* in_sizes, int n_in,
                              void* d_out, int out_size) {
    const float* x    = (const float*)d_in[0];
    const float* w1   = (const float*)d_in[1];
    const float* w2   = (const float*)d_in[2];
    const float* bias = (const float*)d_in[3];
    float* out = (float*)d_out;

    ws_kernel<<<(C_IN * S_TOTAL / 4) / 256, 256>>>(w1);

    dim3 grid(S_TOTAL / S_TILE, B_TOTAL / B_PER_BLK);   // (256, 8) = 2048 blocks
    fused_kernel<<<grid, THREADS>>>(x, w2, bias, out);
}